// round 2
// baseline (speedup 1.0000x reference)
#include <cuda_runtime.h>
#include <math.h>

#define TOK   65536          // B * H * W = 16 * 64 * 64
#define DIMC  256
#define QKVN  768
#define MLPH  1024

// ---------------- scratch (static device globals; no allocation) ----------------
__device__ float g_x   [TOK * DIMC];   // residual stream (mutable copy of input)
__device__ float g_xn  [TOK * DIMC];   // layernorm output
__device__ float g_qkv [TOK * QKVN];   // window-ordered qkv
__device__ float g_attn[TOK * DIMC];   // window-ordered attention output
__device__ float g_h   [TOK * MLPH];   // MLP hidden

// window-token index -> image-token index (handles window partition + cyclic shift)
__device__ __forceinline__ int srcmap(int m, int shift) {
    int w = m >> 6, n = m & 63;
    int b = w >> 6, widx = w & 63;
    int wh = widx >> 3, ww = widx & 7;
    int gr = ((wh << 3) + (n >> 3) + shift) & 63;
    int gc = ((ww << 3) + (n & 7) + shift) & 63;
    return (((b << 6) | gr) << 6) | gc;
}

// ---------------- LayerNorm: one block per row, 256 threads ----------------
__global__ __launch_bounds__(256) void ln_k(const float* __restrict__ x,
                                            const float* __restrict__ g,
                                            const float* __restrict__ b,
                                            float* __restrict__ y) {
    __shared__ float red[8];
    int row = blockIdx.x, tid = threadIdx.x;
    float v = x[(size_t)row * DIMC + tid];

    float s = v;
#pragma unroll
    for (int o = 16; o > 0; o >>= 1) s += __shfl_xor_sync(0xffffffffu, s, o);
    if ((tid & 31) == 0) red[tid >> 5] = s;
    __syncthreads();
    float tot = 0.f;
#pragma unroll
    for (int i = 0; i < 8; i++) tot += red[i];
    float mu = tot * (1.f / 256.f);

    float d = v - mu;
    float s2 = d * d;
#pragma unroll
    for (int o = 16; o > 0; o >>= 1) s2 += __shfl_xor_sync(0xffffffffu, s2, o);
    __syncthreads();
    if ((tid & 31) == 0) red[tid >> 5] = s2;
    __syncthreads();
    float var = 0.f;
#pragma unroll
    for (int i = 0; i < 8; i++) var += red[i];
    var *= (1.f / 256.f);

    y[(size_t)row * DIMC + tid] = d * rsqrtf(var + 1e-5f) * g[tid] + b[tid];
}

// ---------------- Generic SGEMM 128x128x8, 256 threads, 8x8 per thread ----------------
// MODE 0: A rows gathered via srcmap (QKV);        C = A@B + bias
// MODE 1: C rows scattered via srcmap, +=  (proj); residual add into x
// MODE 2: C = gelu(A@B + bias)               (fc1)
// MODE 3: C = R + (A@B + bias)               (fc2)
template <int MODE>
__global__ __launch_bounds__(256) void gemm_k(const float* __restrict__ A,
                                              const float* __restrict__ B,
                                              const float* __restrict__ bias,
                                              float* __restrict__ C,
                                              const float* __restrict__ R,
                                              int K, int N, int shift) {
    __shared__ float As[8][128];   // transposed A tile
    __shared__ float Bs[8][128];

    int tid = threadIdx.x;
    int tx = tid & 15, ty = tid >> 4;
    int bm = blockIdx.y << 7, bn = blockIdx.x << 7;

    int aRow = tid >> 1, aCol = (tid & 1) << 2;
    int am = bm + aRow;
    int pr = (MODE == 0) ? srcmap(am, shift) : am;
    const float* Ap = A + (size_t)pr * K + aCol;

    int bRow = tid >> 5, bCol = (tid & 31) << 2;
    const float* Bp = B + (size_t)bRow * N + bn + bCol;

    float acc[8][8];
#pragma unroll
    for (int i = 0; i < 8; i++)
#pragma unroll
        for (int j = 0; j < 8; j++) acc[i][j] = 0.f;

    for (int k0 = 0; k0 < K; k0 += 8) {
        float4 a4 = *(const float4*)(Ap + k0);
        float4 b4 = *(const float4*)(Bp + (size_t)k0 * N);
        __syncthreads();
        As[aCol + 0][aRow] = a4.x;
        As[aCol + 1][aRow] = a4.y;
        As[aCol + 2][aRow] = a4.z;
        As[aCol + 3][aRow] = a4.w;
        *(float4*)&Bs[bRow][bCol] = b4;
        __syncthreads();
#pragma unroll
        for (int kk = 0; kk < 8; kk++) {
            float a[8], b[8];
            *(float4*)(a)     = *(const float4*)&As[kk][(ty << 3)];
            *(float4*)(a + 4) = *(const float4*)&As[kk][(ty << 3) + 4];
            *(float4*)(b)     = *(const float4*)&Bs[kk][(tx << 3)];
            *(float4*)(b + 4) = *(const float4*)&Bs[kk][(tx << 3) + 4];
#pragma unroll
            for (int i = 0; i < 8; i++)
#pragma unroll
                for (int j = 0; j < 8; j++) acc[i][j] = fmaf(a[i], b[j], acc[i][j]);
        }
    }

#pragma unroll
    for (int i = 0; i < 8; i++) {
        int row = bm + (ty << 3) + i;
        int drow = (MODE == 1) ? srcmap(row, shift) : row;
#pragma unroll
        for (int j = 0; j < 8; j++) {
            int col = bn + (tx << 3) + j;
            float v = acc[i][j] + bias[col];
            size_t o = (size_t)drow * N + col;
            if constexpr (MODE == 0) {
                C[o] = v;
            } else if constexpr (MODE == 1) {
                C[o] += v;                       // bijective scatter -> race-free
            } else if constexpr (MODE == 2) {
                C[o] = 0.5f * v * (1.0f + erff(v * 0.70710678118654752f));
            } else {
                C[o] = R[o] + v;
            }
        }
    }
}

// ---------------- Windowed attention: one block per (window, head) ----------------
__global__ __launch_bounds__(256) void attn_k(const float* __restrict__ qkv,
                                              const float* __restrict__ rpb,
                                              float* __restrict__ out,
                                              int shifted) {
    __shared__ float Qs[64][33], Ks[64][33], Vs[64][33];
    __shared__ float S[64][65];

    int w = blockIdx.x >> 3, h = blockIdx.x & 7;
    int tid = threadIdx.x;
    const float scale = 0.17677669529663687f;   // (32)^-0.5

    size_t base = (size_t)w * 64 * QKVN;
    for (int e = tid; e < 2048; e += 256) {
        int i = e >> 5, d = e & 31;
        size_t ro = base + (size_t)i * QKVN + h * 32 + d;
        Qs[i][d] = qkv[ro] * scale;
        Ks[i][d] = qkv[ro + 256];
        Vs[i][d] = qkv[ro + 512];
    }
    __syncthreads();

    int wh = (w & 63) >> 3, ww = w & 7;
    for (int e = tid; e < 4096; e += 256) {
        int i = e >> 6, j = e & 63;
        float s = 0.f;
#pragma unroll
        for (int d = 0; d < 32; d++) s = fmaf(Qs[i][d], Ks[j][d], s);
        int ri = i >> 3, ci = i & 7, rj = j >> 3, cj = j & 7;
        int idx = (ri - rj + 7) * 15 + (ci - cj + 7);
        s += rpb[idx * 8 + h];
        if (shifted) {
            int li = ((wh == 7) ? (ri < 4 ? 1 : 2) : 0) * 3 + ((ww == 7) ? (ci < 4 ? 1 : 2) : 0);
            int lj = ((wh == 7) ? (rj < 4 ? 1 : 2) : 0) * 3 + ((ww == 7) ? (cj < 4 ? 1 : 2) : 0);
            if (li != lj) s -= 100.0f;
        }
        S[i][j] = s;
    }
    __syncthreads();

    if (tid < 64) {
        float m = -1e30f;
#pragma unroll
        for (int j = 0; j < 64; j++) m = fmaxf(m, S[tid][j]);
        float sum = 0.f;
#pragma unroll
        for (int j = 0; j < 64; j++) {
            float e = expf(S[tid][j] - m);
            S[tid][j] = e;
            sum += e;
        }
        float inv = 1.f / sum;
#pragma unroll
        for (int j = 0; j < 64; j++) S[tid][j] *= inv;
    }
    __syncthreads();

    for (int e = tid; e < 2048; e += 256) {
        int i = e >> 5, d = e & 31;
        float o = 0.f;
#pragma unroll
        for (int j = 0; j < 64; j++) o = fmaf(S[i][j], Vs[j][d], o);
        out[(size_t)(w * 64 + i) * DIMC + h * 32 + d] = o;
    }
}

// ---------------- launch ----------------
extern "C" void kernel_launch(void* const* d_in, const int* in_sizes, int n_in,
                              void* d_out, int out_size) {
    float *xg, *xn, *qkvb, *attnb, *hb;
    cudaGetSymbolAddress((void**)&xg, g_x);
    cudaGetSymbolAddress((void**)&xn, g_xn);
    cudaGetSymbolAddress((void**)&qkvb, g_qkv);
    cudaGetSymbolAddress((void**)&attnb, g_attn);
    cudaGetSymbolAddress((void**)&hb, g_h);

    const float* X = (const float*)d_in[0];
    // input buffer must stay pristine across graph replays -> work on a copy
    cudaMemcpyAsync(xg, X, (size_t)TOK * DIMC * sizeof(float), cudaMemcpyDeviceToDevice);

    for (int blk = 0; blk < 2; blk++) {
        const float* const* P = (const float* const*)(d_in + 1 + blk * 13);
        const float *n1g = P[0], *n1b = P[1], *qkvw = P[2], *qkvbias = P[3], *rpb = P[4];
        const float *pw = P[5], *pb = P[6], *n2g = P[7], *n2b = P[8];
        const float *f1w = P[9], *f1b = P[10], *f2w = P[11], *f2b = P[12];
        int shift = blk ? 4 : 0;

        // LN1
        ln_k<<<TOK, 256>>>(xg, n1g, n1b, xn);
        // QKV gemm with fused roll + window-partition gather
        gemm_k<0><<<dim3(QKVN / 128, TOK / 128), 256>>>(xn, qkvw, qkvbias, qkvb, nullptr, DIMC, QKVN, shift);
        // windowed attention (+rel-pos bias, +shift mask)
        attn_k<<<8192, 256>>>(qkvb, rpb, attnb, blk);
        // proj gemm with fused window-reverse + un-roll scatter, residual add
        gemm_k<1><<<dim3(DIMC / 128, TOK / 128), 256>>>(attnb, pw, pb, xg, nullptr, DIMC, DIMC, shift);
        // LN2
        ln_k<<<TOK, 256>>>(xg, n2g, n2b, xn);
        // fc1 + exact GELU
        gemm_k<2><<<dim3(MLPH / 128, TOK / 128), 256>>>(xn, f1w, f1b, hb, nullptr, DIMC, MLPH, 0);
        // fc2 + residual add (block 1 writes final result straight to d_out)
        float* dst = (blk == 0) ? xg : (float*)d_out;
        gemm_k<3><<<dim3(DIMC / 128, TOK / 128), 256>>>(hb, f2w, f2b, dst, xg, MLPH, DIMC, 0);
    }
}

// round 4
// speedup vs baseline: 1.5603x; 1.5603x over previous
#include <cuda_runtime.h>
#include <math.h>

#define TOK   65536          // B * H * W = 16 * 64 * 64
#define DIMC  256
#define QKVN  768
#define MLPH  1024

// ---------------- scratch (static device globals; no allocation) ----------------
__device__ float g_x   [TOK * DIMC];   // residual stream (mutable copy of input)
__device__ float g_xn  [TOK * DIMC];   // layernorm output
__device__ float g_qkv [TOK * QKVN];   // window-ordered qkv
__device__ float g_attn[TOK * DIMC];   // window-ordered attention output
__device__ float g_h   [TOK * MLPH];   // MLP hidden

// window-token index -> image-token index (handles window partition + cyclic shift)
__device__ __forceinline__ int srcmap(int m, int shift) {
    int w = m >> 6, n = m & 63;
    int b = w >> 6, widx = w & 63;
    int wh = widx >> 3, ww = widx & 7;
    int gr = ((wh << 3) + (n >> 3) + shift) & 63;
    int gc = ((ww << 3) + (n & 7) + shift) & 63;
    return (((b << 6) | gr) << 6) | gc;
}

__device__ __forceinline__ unsigned f2tf(float f) {
    unsigned u;
    asm("cvt.rna.tf32.f32 %0, %1;" : "=r"(u) : "f"(f));
    return u;
}

__device__ __forceinline__ void mma_tf32(float c[4], const unsigned a[4], const unsigned b[2]) {
    asm volatile(
        "mma.sync.aligned.m16n8k8.row.col.f32.tf32.tf32.f32 "
        "{%0,%1,%2,%3}, {%4,%5,%6,%7}, {%8,%9}, {%0,%1,%2,%3};\n"
        : "+f"(c[0]), "+f"(c[1]), "+f"(c[2]), "+f"(c[3])
        : "r"(a[0]), "r"(a[1]), "r"(a[2]), "r"(a[3]), "r"(b[0]), "r"(b[1]));
}

// ---------------- LayerNorm: one block per row, 256 threads ----------------
__global__ __launch_bounds__(256) void ln_k(const float* __restrict__ x,
                                            const float* __restrict__ g,
                                            const float* __restrict__ b,
                                            float* __restrict__ y) {
    __shared__ float red[8];
    int row = blockIdx.x, tid = threadIdx.x;
    float v = x[(size_t)row * DIMC + tid];

    float s = v;
#pragma unroll
    for (int o = 16; o > 0; o >>= 1) s += __shfl_xor_sync(0xffffffffu, s, o);
    if ((tid & 31) == 0) red[tid >> 5] = s;
    __syncthreads();
    float tot = 0.f;
#pragma unroll
    for (int i = 0; i < 8; i++) tot += red[i];
    float mu = tot * (1.f / 256.f);

    float d = v - mu;
    float s2 = d * d;
#pragma unroll
    for (int o = 16; o > 0; o >>= 1) s2 += __shfl_xor_sync(0xffffffffu, s2, o);
    __syncthreads();
    if ((tid & 31) == 0) red[tid >> 5] = s2;
    __syncthreads();
    float var = 0.f;
#pragma unroll
    for (int i = 0; i < 8; i++) var += red[i];
    var *= (1.f / 256.f);

    y[(size_t)row * DIMC + tid] = d * rsqrtf(var + 1e-5f) * g[tid] + b[tid];
}

// ---------------- tf32 tensor-core GEMM: 128x256 block, 8 warps, warp 64x64 ----------------
// MODE 0: A rows gathered via srcmap (QKV);        C = A@B + bias
// MODE 1: C rows scattered via srcmap, +=  (proj)
// MODE 2: C = gelu(A@B + bias)               (fc1)
// MODE 3: C = R + (A@B + bias)               (fc2)
template <int MODE>
__global__ __launch_bounds__(256, 1) void tgemm(const float* __restrict__ A,
                                                const float* __restrict__ B,
                                                const float* __restrict__ bias,
                                                float* __restrict__ C,
                                                const float* __restrict__ R,
                                                int K, int N, int shift) {
    // A: 128 rows x 8 k, stride 12 (bank = 12*g + tig -> conflict-free LDS.32)
    // B: 8 k x 256 n, stride 264 (bank = 8*tig + g -> conflict-free LDS.32)
    __shared__ unsigned As[2][128 * 12];
    __shared__ unsigned Bs[2][8 * 264];

    int tid = threadIdx.x;
    int lane = tid & 31, wid = tid >> 5;
    int wm = wid >> 2, wn = wid & 3;        // 2 x 4 warp grid
    int g = lane >> 2, tig = lane & 3;
    int bm = blockIdx.y << 7, bn = blockIdx.x << 8;

    // --- staging thread maps ---
    int ar = tid >> 1, ac = (tid & 1) << 2;           // A: 2 float4 per row
    int agrow = (MODE == 0) ? srcmap(bm + ar, shift) : (bm + ar);
    const float* Aptr = A + (size_t)agrow * K + ac;
    int a_sts = ar * 12 + ac;

    int bk = tid & 7, bn4 = tid >> 3;                  // B: k-major
    const float* Bptr = B + (size_t)bk * N + bn + (bn4 << 2);
    int b_sts = bk * 264 + (bn4 << 2);

    float acc[4][8][4];
#pragma unroll
    for (int mi = 0; mi < 4; mi++)
#pragma unroll
        for (int ni = 0; ni < 8; ni++)
#pragma unroll
            for (int e = 0; e < 4; e++) acc[mi][ni][e] = 0.f;

    const int NC = K >> 3;

    float4 ra = *(const float4*)(Aptr);
    float4 rb0 = *(const float4*)(Bptr);
    float4 rb1 = *(const float4*)(Bptr + 128);

    {
        unsigned* as = As[0];
        unsigned* bs = Bs[0];
        *(uint4*)&as[a_sts] = make_uint4(f2tf(ra.x), f2tf(ra.y), f2tf(ra.z), f2tf(ra.w));
        *(uint4*)&bs[b_sts] = make_uint4(f2tf(rb0.x), f2tf(rb0.y), f2tf(rb0.z), f2tf(rb0.w));
        *(uint4*)&bs[b_sts + 128] = make_uint4(f2tf(rb1.x), f2tf(rb1.y), f2tf(rb1.z), f2tf(rb1.w));
    }
    __syncthreads();

    int buf = 0;
    for (int c = 0; c < NC; c++) {
        if (c + 1 < NC) {
            ra = *(const float4*)(Aptr + (c + 1) * 8);
            rb0 = *(const float4*)(Bptr + (size_t)(c + 1) * 8 * N);
            rb1 = *(const float4*)(Bptr + (size_t)(c + 1) * 8 * N + 128);
        }

        const unsigned* as = As[buf];
        const unsigned* bs = Bs[buf];
        unsigned af[4][4], bf[8][2];
#pragma unroll
        for (int mi = 0; mi < 4; mi++) {
            int r0 = (wm * 64 + mi * 16 + g) * 12;
            af[mi][0] = as[r0 + tig];
            af[mi][1] = as[r0 + 96 + tig];        // +8 rows
            af[mi][2] = as[r0 + tig + 4];
            af[mi][3] = as[r0 + 96 + tig + 4];
        }
#pragma unroll
        for (int ni = 0; ni < 8; ni++) {
            int cix = wn * 64 + ni * 8 + g;
            bf[ni][0] = bs[tig * 264 + cix];
            bf[ni][1] = bs[(tig + 4) * 264 + cix];
        }
#pragma unroll
        for (int mi = 0; mi < 4; mi++)
#pragma unroll
            for (int ni = 0; ni < 8; ni++) mma_tf32(acc[mi][ni], af[mi], bf[ni]);

        if (c + 1 < NC) {
            unsigned* asn = As[buf ^ 1];
            unsigned* bsn = Bs[buf ^ 1];
            *(uint4*)&asn[a_sts] = make_uint4(f2tf(ra.x), f2tf(ra.y), f2tf(ra.z), f2tf(ra.w));
            *(uint4*)&bsn[b_sts] = make_uint4(f2tf(rb0.x), f2tf(rb0.y), f2tf(rb0.z), f2tf(rb0.w));
            *(uint4*)&bsn[b_sts + 128] = make_uint4(f2tf(rb1.x), f2tf(rb1.y), f2tf(rb1.z), f2tf(rb1.w));
        }
        __syncthreads();
        buf ^= 1;
    }

    // --- epilogue ---
#pragma unroll
    for (int mi = 0; mi < 4; mi++) {
        int r0 = bm + wm * 64 + mi * 16 + g;
        int r1 = r0 + 8;
        int d0 = (MODE == 1) ? srcmap(r0, shift) : r0;
        int d1 = (MODE == 1) ? srcmap(r1, shift) : r1;
#pragma unroll
        for (int ni = 0; ni < 8; ni++) {
            int col = bn + wn * 64 + ni * 8 + (tig << 1);
            float bv0 = bias[col], bv1 = bias[col + 1];
            float v00 = acc[mi][ni][0] + bv0, v01 = acc[mi][ni][1] + bv1;
            float v10 = acc[mi][ni][2] + bv0, v11 = acc[mi][ni][3] + bv1;
            size_t o0 = (size_t)d0 * N + col;
            size_t o1 = (size_t)d1 * N + col;
            if constexpr (MODE == 0) {
                *(float2*)&C[o0] = make_float2(v00, v01);
                *(float2*)&C[o1] = make_float2(v10, v11);
            } else if constexpr (MODE == 1) {
                float2 p0 = *(const float2*)&C[o0];
                float2 p1 = *(const float2*)&C[o1];
                *(float2*)&C[o0] = make_float2(p0.x + v00, p0.y + v01);
                *(float2*)&C[o1] = make_float2(p1.x + v10, p1.y + v11);
            } else if constexpr (MODE == 2) {
                const float is2 = 0.70710678118654752f;
                *(float2*)&C[o0] = make_float2(0.5f * v00 * (1.f + erff(v00 * is2)),
                                               0.5f * v01 * (1.f + erff(v01 * is2)));
                *(float2*)&C[o1] = make_float2(0.5f * v10 * (1.f + erff(v10 * is2)),
                                               0.5f * v11 * (1.f + erff(v11 * is2)));
            } else {
                float2 p0 = *(const float2*)&R[o0];
                float2 p1 = *(const float2*)&R[o1];
                *(float2*)&C[o0] = make_float2(p0.x + v00, p0.y + v01);
                *(float2*)&C[o1] = make_float2(p1.x + v10, p1.y + v11);
            }
        }
    }
}

// ---------------- Windowed attention: one block per (window, head) ----------------
__global__ __launch_bounds__(256) void attn_k(const float* __restrict__ qkv,
                                              const float* __restrict__ rpb,
                                              float* __restrict__ out,
                                              int shifted) {
    __shared__ float Qs[64][33], Ks[64][33], Vs[64][33];
    __shared__ float S[64][65];

    int w = blockIdx.x >> 3, h = blockIdx.x & 7;
    int tid = threadIdx.x;
    const float scale = 0.17677669529663687f;   // (32)^-0.5

    size_t base = (size_t)w * 64 * QKVN;
    for (int e = tid; e < 2048; e += 256) {
        int i = e >> 5, d = e & 31;
        size_t ro = base + (size_t)i * QKVN + h * 32 + d;
        Qs[i][d] = qkv[ro] * scale;
        Ks[i][d] = qkv[ro + 256];
        Vs[i][d] = qkv[ro + 512];
    }
    __syncthreads();

    int wh = (w & 63) >> 3, ww = w & 7;
    for (int e = tid; e < 4096; e += 256) {
        int i = e >> 6, j = e & 63;
        float s = 0.f;
#pragma unroll
        for (int d = 0; d < 32; d++) s = fmaf(Qs[i][d], Ks[j][d], s);
        int ri = i >> 3, ci = i & 7, rj = j >> 3, cj = j & 7;
        int idx = (ri - rj + 7) * 15 + (ci - cj + 7);
        s += rpb[idx * 8 + h];
        if (shifted) {
            int li = ((wh == 7) ? (ri < 4 ? 1 : 2) : 0) * 3 + ((ww == 7) ? (ci < 4 ? 1 : 2) : 0);
            int lj = ((wh == 7) ? (rj < 4 ? 1 : 2) : 0) * 3 + ((ww == 7) ? (cj < 4 ? 1 : 2) : 0);
            if (li != lj) s -= 100.0f;
        }
        S[i][j] = s;
    }
    __syncthreads();

    if (tid < 64) {
        float m = -1e30f;
#pragma unroll
        for (int j = 0; j < 64; j++) m = fmaxf(m, S[tid][j]);
        float sum = 0.f;
#pragma unroll
        for (int j = 0; j < 64; j++) {
            float e = expf(S[tid][j] - m);
            S[tid][j] = e;
            sum += e;
        }
        float inv = 1.f / sum;
#pragma unroll
        for (int j = 0; j < 64; j++) S[tid][j] *= inv;
    }
    __syncthreads();

    for (int e = tid; e < 2048; e += 256) {
        int i = e >> 5, d = e & 31;
        float o = 0.f;
#pragma unroll
        for (int j = 0; j < 64; j++) o = fmaf(S[i][j], Vs[j][d], o);
        out[(size_t)(w * 64 + i) * DIMC + h * 32 + d] = o;
    }
}

// ---------------- launch ----------------
extern "C" void kernel_launch(void* const* d_in, const int* in_sizes, int n_in,
                              void* d_out, int out_size) {
    float *xg, *xn, *qkvb, *attnb, *hb;
    cudaGetSymbolAddress((void**)&xg, g_x);
    cudaGetSymbolAddress((void**)&xn, g_xn);
    cudaGetSymbolAddress((void**)&qkvb, g_qkv);
    cudaGetSymbolAddress((void**)&attnb, g_attn);
    cudaGetSymbolAddress((void**)&hb, g_h);

    const float* X = (const float*)d_in[0];
    // input buffer must stay pristine across graph replays -> work on a copy
    cudaMemcpyAsync(xg, X, (size_t)TOK * DIMC * sizeof(float), cudaMemcpyDeviceToDevice);

    for (int blk = 0; blk < 2; blk++) {
        const float* const* P = (const float* const*)(d_in + 1 + blk * 13);
        const float *n1g = P[0], *n1b = P[1], *qkvw = P[2], *qkvbias = P[3], *rpb = P[4];
        const float *pw = P[5], *pb = P[6], *n2g = P[7], *n2b = P[8];
        const float *f1w = P[9], *f1b = P[10], *f2w = P[11], *f2b = P[12];
        int shift = blk ? 4 : 0;

        // LN1
        ln_k<<<TOK, 256>>>(xg, n1g, n1b, xn);
        // QKV gemm with fused roll + window-partition gather
        tgemm<0><<<dim3(QKVN / 256, TOK / 128), 256>>>(xn, qkvw, qkvbias, qkvb, nullptr, DIMC, QKVN, shift);
        // windowed attention (+rel-pos bias, +shift mask)
        attn_k<<<8192, 256>>>(qkvb, rpb, attnb, blk);
        // proj gemm with fused window-reverse + un-roll scatter, residual add
        tgemm<1><<<dim3(DIMC / 256, TOK / 128), 256>>>(attnb, pw, pb, xg, nullptr, DIMC, DIMC, shift);
        // LN2
        ln_k<<<TOK, 256>>>(xg, n2g, n2b, xn);
        // fc1 + exact GELU
        tgemm<2><<<dim3(MLPH / 256, TOK / 128), 256>>>(xn, f1w, f1b, hb, nullptr, DIMC, MLPH, 0);
        // fc2 + residual add (block 1 writes final result straight to d_out)
        float* dst = (blk == 0) ? xg : (float*)d_out;
        tgemm<3><<<dim3(DIMC / 256, TOK / 128), 256>>>(hb, f2w, f2b, dst, xg, MLPH, DIMC, 0);
    }
}

// round 11
// speedup vs baseline: 2.2270x; 1.4273x over previous
#include <cuda_runtime.h>
#include <math.h>

#define TOK   65536          // B * H * W
#define DIMC  256
#define QKVN  768
#define MLPH  1024

#define STAGES 4
#define BK     16
#define A_STRIDE 20          // 16 k + 4 pad (floats)
#define B_STRIDE 264         // 256 n + 8 pad (floats)
#define ASZ (128 * A_STRIDE)
#define BSZ (BK * B_STRIDE)
#define SSZ (ASZ + BSZ)
#define SMEM_BYTES (STAGES * SSZ * 4)

// ---------------- scratch (static device globals; no allocation) ----------------
__device__ float g_x   [TOK * DIMC];
__device__ float g_xn  [TOK * DIMC];
__device__ float g_qkv [TOK * QKVN];
__device__ float g_attn[TOK * DIMC];
__device__ float g_h   [TOK * MLPH];
__device__ float g_w   [2][786432];   // tf32-rounded weights per block: qkvw|pw|f1w|f2w

__device__ __forceinline__ int srcmap(int m, int shift) {
    int w = m >> 6, n = m & 63;
    int b = w >> 6, widx = w & 63;
    int wh = widx >> 3, ww = widx & 7;
    int gr = ((wh << 3) + (n >> 3) + shift) & 63;
    int gc = ((ww << 3) + (n & 7) + shift) & 63;
    return (((b << 6) | gr) << 6) | gc;
}

__device__ __forceinline__ unsigned f2tf(float f) {
    unsigned u;
    asm("cvt.rna.tf32.f32 %0, %1;" : "=r"(u) : "f"(f));
    return u;
}
__device__ __forceinline__ float rtf(float f) { return __uint_as_float(f2tf(f)); }

__device__ __forceinline__ void mma_tf32(float c[4], const unsigned a[4], const unsigned b[2]) {
    asm volatile(
        "mma.sync.aligned.m16n8k8.row.col.f32.tf32.tf32.f32 "
        "{%0,%1,%2,%3}, {%4,%5,%6,%7}, {%8,%9}, {%0,%1,%2,%3};\n"
        : "+f"(c[0]), "+f"(c[1]), "+f"(c[2]), "+f"(c[3])
        : "r"(a[0]), "r"(a[1]), "r"(a[2]), "r"(a[3]), "r"(b[0]), "r"(b[1]));
}

__device__ __forceinline__ void cpa16(float* dst, const float* src) {
    unsigned d = (unsigned)__cvta_generic_to_shared(dst);
    asm volatile("cp.async.cg.shared.global [%0], [%1], 16;\n" :: "r"(d), "l"(src));
}
__device__ __forceinline__ void cp_commit() { asm volatile("cp.async.commit_group;\n" ::: "memory"); }
template <int N> __device__ __forceinline__ void cp_wait() {
    asm volatile("cp.async.wait_group %0;\n" :: "n"(N) : "memory");
}

// ---------------- weight -> tf32 rounding ----------------
__global__ __launch_bounds__(256) void cvt_k(const float* __restrict__ w, float* __restrict__ o, int n) {
    int i = blockIdx.x * 256 + threadIdx.x;
    if (i < n) o[i] = rtf(w[i]);
}

// ---------------- LayerNorm (writes tf32-rounded output) ----------------
__global__ __launch_bounds__(256) void ln_k(const float* __restrict__ x,
                                            const float* __restrict__ g,
                                            const float* __restrict__ b,
                                            float* __restrict__ y) {
    __shared__ float red[8];
    int row = blockIdx.x, tid = threadIdx.x;
    float v = x[(size_t)row * DIMC + tid];

    float s = v;
#pragma unroll
    for (int o = 16; o > 0; o >>= 1) s += __shfl_xor_sync(0xffffffffu, s, o);
    if ((tid & 31) == 0) red[tid >> 5] = s;
    __syncthreads();
    float tot = 0.f;
#pragma unroll
    for (int i = 0; i < 8; i++) tot += red[i];
    float mu = tot * (1.f / 256.f);

    float d = v - mu;
    float s2 = d * d;
#pragma unroll
    for (int o = 16; o > 0; o >>= 1) s2 += __shfl_xor_sync(0xffffffffu, s2, o);
    __syncthreads();
    if ((tid & 31) == 0) red[tid >> 5] = s2;
    __syncthreads();
    float var = 0.f;
#pragma unroll
    for (int i = 0; i < 8; i++) var += red[i];
    var *= (1.f / 256.f);

    y[(size_t)row * DIMC + tid] = rtf(d * rsqrtf(var + 1e-5f) * g[tid] + b[tid]);
}

// ---------------- tf32 GEMM: 128x256 block, cp.async 4-stage, BK=16 ----------------
// MODE 0: A gathered via srcmap; C = A@B+bias   (qkv)
// MODE 1: C scattered via srcmap, += (proj)
// MODE 2: C = tf32round(gelu(A@B+bias))         (fc1 -> feeds fc2)
// MODE 3: C = R + (A@B+bias)                    (fc2)
template <int MODE>
__global__ __launch_bounds__(256, 1) void tgemm(const float* __restrict__ A,
                                                const float* __restrict__ B,
                                                const float* __restrict__ bias,
                                                float* __restrict__ C,
                                                const float* __restrict__ R,
                                                int K, int N, int shift) {
    extern __shared__ float sm[];

    int tid = threadIdx.x;
    int lane = tid & 31, wid = tid >> 5;
    int wm = wid >> 2, wn = wid & 3;
    int g = lane >> 2, tig = lane & 3;
    int bm = blockIdx.y << 7, bn = blockIdx.x << 8;

    // ---- cp.async staging maps ----
    // A: 128x16 floats = 512 float4; thread t -> rows (t>>2) and (t>>2)+64, col4 = t&3
    int arow0 = tid >> 2, ac = (tid & 3) << 2;
    int gr0 = (MODE == 0) ? srcmap(bm + arow0, shift) : (bm + arow0);
    int gr1 = (MODE == 0) ? srcmap(bm + arow0 + 64, shift) : (bm + arow0 + 64);
    const float* aptr0 = A + (size_t)gr0 * K + ac;
    const float* aptr1 = A + (size_t)gr1 * K + ac;
    int asd0 = arow0 * A_STRIDE + ac;
    int asd1 = (arow0 + 64) * A_STRIDE + ac;
    // B: 16x256 floats = 1024 float4; thread t -> rows (t>>6)+{0,4,8,12}, col4 = t&63
    int brow = tid >> 6, bc = (tid & 63) << 2;
    const float* bptr = B + (size_t)brow * N + bn + bc;
    int bsd = brow * B_STRIDE + bc;

    float acc[4][8][4];
#pragma unroll
    for (int mi = 0; mi < 4; mi++)
#pragma unroll
        for (int ni = 0; ni < 8; ni++)
#pragma unroll
            for (int e = 0; e < 4; e++) acc[mi][ni][e] = 0.f;

    const int NC = K >> 4;

#define ISSUE(slot, kc)                                                           \
    {                                                                             \
        float* d = sm + (slot) * SSZ;                                             \
        int k0 = (kc) << 4;                                                       \
        cpa16(d + asd0, aptr0 + k0);                                              \
        cpa16(d + asd1, aptr1 + k0);                                              \
        float* bd = d + ASZ;                                                      \
        const float* bs_ = bptr + (size_t)k0 * N;                                 \
        cpa16(bd + bsd,                bs_);                                      \
        cpa16(bd + bsd + 4 * B_STRIDE, bs_ + (size_t)4 * N);                      \
        cpa16(bd + bsd + 8 * B_STRIDE, bs_ + (size_t)8 * N);                      \
        cpa16(bd + bsd + 12 * B_STRIDE, bs_ + (size_t)12 * N);                    \
    }

#pragma unroll
    for (int s = 0; s < STAGES - 1; s++) {
        ISSUE(s, s);
        cp_commit();
    }

    for (int c = 0; c < NC; c++) {
        cp_wait<STAGES - 2>();
        __syncthreads();

        if (c + STAGES - 1 < NC) ISSUE((c + STAGES - 1) & (STAGES - 1), c + STAGES - 1);
        cp_commit();

        const unsigned* as = (const unsigned*)(sm + (c & (STAGES - 1)) * SSZ);
        const unsigned* bs = as + ASZ;
#pragma unroll
        for (int s8 = 0; s8 < 2; s8++) {
            int kb = s8 << 3;
            unsigned af[4][4], bf[8][2];
#pragma unroll
            for (int mi = 0; mi < 4; mi++) {
                int r0 = (wm * 64 + mi * 16 + g) * A_STRIDE + kb;
                af[mi][0] = as[r0 + tig];
                af[mi][1] = as[r0 + 8 * A_STRIDE + tig];
                af[mi][2] = as[r0 + tig + 4];
                af[mi][3] = as[r0 + 8 * A_STRIDE + tig + 4];
            }
#pragma unroll
            for (int ni = 0; ni < 8; ni++) {
                int cix = wn * 64 + ni * 8 + g;
                bf[ni][0] = bs[(kb + tig) * B_STRIDE + cix];
                bf[ni][1] = bs[(kb + tig + 4) * B_STRIDE + cix];
            }
#pragma unroll
            for (int mi = 0; mi < 4; mi++)
#pragma unroll
                for (int ni = 0; ni < 8; ni++) mma_tf32(acc[mi][ni], af[mi], bf[ni]);
        }
    }
#undef ISSUE

    // ---- epilogue ----
#pragma unroll
    for (int mi = 0; mi < 4; mi++) {
        int r0 = bm + wm * 64 + mi * 16 + g;
        int r1 = r0 + 8;
        int d0 = (MODE == 1) ? srcmap(r0, shift) : r0;
        int d1 = (MODE == 1) ? srcmap(r1, shift) : r1;
#pragma unroll
        for (int ni = 0; ni < 8; ni++) {
            int col = bn + wn * 64 + ni * 8 + (tig << 1);
            float bv0 = bias[col], bv1 = bias[col + 1];
            float v00 = acc[mi][ni][0] + bv0, v01 = acc[mi][ni][1] + bv1;
            float v10 = acc[mi][ni][2] + bv0, v11 = acc[mi][ni][3] + bv1;
            size_t o0 = (size_t)d0 * N + col;
            size_t o1 = (size_t)d1 * N + col;
            if constexpr (MODE == 0) {
                *(float2*)&C[o0] = make_float2(v00, v01);
                *(float2*)&C[o1] = make_float2(v10, v11);
            } else if constexpr (MODE == 1) {
                float2 p0 = *(const float2*)&C[o0];
                float2 p1 = *(const float2*)&C[o1];
                *(float2*)&C[o0] = make_float2(p0.x + v00, p0.y + v01);
                *(float2*)&C[o1] = make_float2(p1.x + v10, p1.y + v11);
            } else if constexpr (MODE == 2) {
                const float is2 = 0.70710678118654752f;
                *(float2*)&C[o0] = make_float2(rtf(0.5f * v00 * (1.f + erff(v00 * is2))),
                                               rtf(0.5f * v01 * (1.f + erff(v01 * is2))));
                *(float2*)&C[o1] = make_float2(rtf(0.5f * v10 * (1.f + erff(v10 * is2))),
                                               rtf(0.5f * v11 * (1.f + erff(v11 * is2))));
            } else {
                float2 p0 = *(const float2*)&R[o0];
                float2 p1 = *(const float2*)&R[o1];
                *(float2*)&C[o0] = make_float2(p0.x + v00, p0.y + v01);
                *(float2*)&C[o1] = make_float2(p1.x + v10, p1.y + v11);
            }
        }
    }
}

// ---------------- Windowed attention (writes tf32-rounded output) ----------------
__global__ __launch_bounds__(256) void attn_k(const float* __restrict__ qkv,
                                              const float* __restrict__ rpb,
                                              float* __restrict__ out,
                                              int shifted) {
    __shared__ float Qs[64][33], Ks[64][33], Vs[64][33];
    __shared__ float S[64][65];

    int w = blockIdx.x >> 3, h = blockIdx.x & 7;
    int tid = threadIdx.x;
    const float scale = 0.17677669529663687f;

    size_t base = (size_t)w * 64 * QKVN;
    for (int e = tid; e < 2048; e += 256) {
        int i = e >> 5, d = e & 31;
        size_t ro = base + (size_t)i * QKVN + h * 32 + d;
        Qs[i][d] = qkv[ro] * scale;
        Ks[i][d] = qkv[ro + 256];
        Vs[i][d] = qkv[ro + 512];
    }
    __syncthreads();

    int wh = (w & 63) >> 3, ww = w & 7;
    for (int e = tid; e < 4096; e += 256) {
        int i = e >> 6, j = e & 63;
        float s = 0.f;
#pragma unroll
        for (int d = 0; d < 32; d++) s = fmaf(Qs[i][d], Ks[j][d], s);
        int ri = i >> 3, ci = i & 7, rj = j >> 3, cj = j & 7;
        int idx = (ri - rj + 7) * 15 + (ci - cj + 7);
        s += rpb[idx * 8 + h];
        if (shifted) {
            int li = ((wh == 7) ? (ri < 4 ? 1 : 2) : 0) * 3 + ((ww == 7) ? (ci < 4 ? 1 : 2) : 0);
            int lj = ((wh == 7) ? (rj < 4 ? 1 : 2) : 0) * 3 + ((ww == 7) ? (cj < 4 ? 1 : 2) : 0);
            if (li != lj) s -= 100.0f;
        }
        S[i][j] = s;
    }
    __syncthreads();

    if (tid < 64) {
        float m = -1e30f;
#pragma unroll
        for (int j = 0; j < 64; j++) m = fmaxf(m, S[tid][j]);
        float sum = 0.f;
#pragma unroll
        for (int j = 0; j < 64; j++) {
            float e = expf(S[tid][j] - m);
            S[tid][j] = e;
            sum += e;
        }
        float inv = 1.f / sum;
#pragma unroll
        for (int j = 0; j < 64; j++) S[tid][j] *= inv;
    }
    __syncthreads();

    for (int e = tid; e < 2048; e += 256) {
        int i = e >> 5, d = e & 31;
        float o = 0.f;
#pragma unroll
        for (int j = 0; j < 64; j++) o = fmaf(S[i][j], Vs[j][d], o);
        out[(size_t)(w * 64 + i) * DIMC + h * 32 + d] = rtf(o);
    }
}

// ---------------- launch ----------------
extern "C" void kernel_launch(void* const* d_in, const int* in_sizes, int n_in,
                              void* d_out, int out_size) {
    float *xg, *xn, *qkvb, *attnb, *hb, *wb;
    cudaGetSymbolAddress((void**)&xg, g_x);
    cudaGetSymbolAddress((void**)&xn, g_xn);
    cudaGetSymbolAddress((void**)&qkvb, g_qkv);
    cudaGetSymbolAddress((void**)&attnb, g_attn);
    cudaGetSymbolAddress((void**)&hb, g_h);
    cudaGetSymbolAddress((void**)&wb, g_w);

    cudaFuncSetAttribute(tgemm<0>, cudaFuncAttributeMaxDynamicSharedMemorySize, SMEM_BYTES);
    cudaFuncSetAttribute(tgemm<1>, cudaFuncAttributeMaxDynamicSharedMemorySize, SMEM_BYTES);
    cudaFuncSetAttribute(tgemm<2>, cudaFuncAttributeMaxDynamicSharedMemorySize, SMEM_BYTES);
    cudaFuncSetAttribute(tgemm<3>, cudaFuncAttributeMaxDynamicSharedMemorySize, SMEM_BYTES);

    const float* X = (const float*)d_in[0];
    cudaMemcpyAsync(xg, X, (size_t)TOK * DIMC * sizeof(float), cudaMemcpyDeviceToDevice);

    // per-block converted-weight layout: qkvw | pw | f1w | f2w
    const int WOFF_P = 196608, WOFF_F1 = 262144, WOFF_F2 = 524288, WSZ = 786432;

    for (int blk = 0; blk < 2; blk++) {
        const float* const* P = (const float* const*)(d_in + 1 + blk * 13);
        cvt_k<<<196608 / 256, 256>>>(P[2], wb + blk * WSZ, 196608);
        cvt_k<<<65536 / 256, 256>>>(P[5], wb + blk * WSZ + WOFF_P, 65536);
        cvt_k<<<262144 / 256, 256>>>(P[9], wb + blk * WSZ + WOFF_F1, 262144);
        cvt_k<<<262144 / 256, 256>>>(P[11], wb + blk * WSZ + WOFF_F2, 262144);
    }

    for (int blk = 0; blk < 2; blk++) {
        const float* const* P = (const float* const*)(d_in + 1 + blk * 13);
        const float *n1g = P[0], *n1b = P[1], *qkvbias = P[3], *rpb = P[4];
        const float *pb = P[6], *n2g = P[7], *n2b = P[8];
        const float *f1b = P[10], *f2b = P[12];
        const float* W = wb + blk * WSZ;
        int shift = blk ? 4 : 0;

        ln_k<<<TOK, 256>>>(xg, n1g, n1b, xn);
        tgemm<0><<<dim3(QKVN / 256, TOK / 128), 256, SMEM_BYTES>>>(xn, W, qkvbias, qkvb, nullptr, DIMC, QKVN, shift);
        attn_k<<<8192, 256>>>(qkvb, rpb, attnb, blk);
        tgemm<1><<<dim3(DIMC / 256, TOK / 128), 256, SMEM_BYTES>>>(attnb, W + WOFF_P, pb, xg, nullptr, DIMC, DIMC, shift);
        ln_k<<<TOK, 256>>>(xg, n2g, n2b, xn);
        tgemm<2><<<dim3(MLPH / 256, TOK / 128), 256, SMEM_BYTES>>>(xn, W + WOFF_F1, f1b, hb, nullptr, DIMC, MLPH, 0);
        float* dst = (blk == 0) ? xg : (float*)d_out;
        tgemm<3><<<dim3(DIMC / 256, TOK / 128), 256, SMEM_BYTES>>>(hb, W + WOFF_F2, f2b, dst, xg, MLPH, DIMC, 0);
    }
}

// round 14
// speedup vs baseline: 2.3770x; 1.0674x over previous
#include <cuda_runtime.h>
#include <math.h>

#define TOK   65536          // B * H * W
#define DIMC  256
#define QKVN  768
#define MLPH  1024

#define STAGES 4
#define BK     16
#define A_STRIDE 20          // 16 k + 4 pad (floats)
#define B_STRIDE 264         // 256 n + 8 pad (floats)
#define ASZ (128 * A_STRIDE)
#define BSZ (BK * B_STRIDE)
#define SSZ (ASZ + BSZ)
#define SMEM_BYTES (STAGES * SSZ * 4)

// ---------------- scratch (static device globals; no allocation) ----------------
__device__ float g_x   [TOK * DIMC];
__device__ float g_xn  [TOK * DIMC];
__device__ float g_qkv [TOK * QKVN];
__device__ float g_attn[TOK * DIMC];
__device__ float g_h   [TOK * MLPH];
__device__ float g_w   [2][786432];   // tf32-rounded weights per block: qkvw|pw|f1w|f2w

__device__ __forceinline__ int srcmap(int m, int shift) {
    int w = m >> 6, n = m & 63;
    int b = w >> 6, widx = w & 63;
    int wh = widx >> 3, ww = widx & 7;
    int gr = ((wh << 3) + (n >> 3) + shift) & 63;
    int gc = ((ww << 3) + (n & 7) + shift) & 63;
    return (((b << 6) | gr) << 6) | gc;
}

__device__ __forceinline__ unsigned f2tf(float f) {
    unsigned u;
    asm("cvt.rna.tf32.f32 %0, %1;" : "=r"(u) : "f"(f));
    return u;
}
__device__ __forceinline__ float rtf(float f) { return __uint_as_float(f2tf(f)); }

__device__ __forceinline__ void mma_tf32(float c[4], const unsigned a[4], const unsigned b[2]) {
    asm volatile(
        "mma.sync.aligned.m16n8k8.row.col.f32.tf32.tf32.f32 "
        "{%0,%1,%2,%3}, {%4,%5,%6,%7}, {%8,%9}, {%0,%1,%2,%3};\n"
        : "+f"(c[0]), "+f"(c[1]), "+f"(c[2]), "+f"(c[3])
        : "r"(a[0]), "r"(a[1]), "r"(a[2]), "r"(a[3]), "r"(b[0]), "r"(b[1]));
}

__device__ __forceinline__ void cpa16(float* dst, const float* src) {
    unsigned d = (unsigned)__cvta_generic_to_shared(dst);
    asm volatile("cp.async.cg.shared.global [%0], [%1], 16;\n" :: "r"(d), "l"(src));
}
__device__ __forceinline__ void cp_commit() { asm volatile("cp.async.commit_group;\n" ::: "memory"); }
template <int N> __device__ __forceinline__ void cp_wait() {
    asm volatile("cp.async.wait_group %0;\n" :: "n"(N) : "memory");
}

// ---------------- weight -> tf32 rounding (4 tensors in one launch) ----------------
// segment sizes: qkvw 196608 | pw 65536 | f1w 262144 | f2w 262144  (total 786432)
__global__ __launch_bounds__(256) void cvt4_k(const float* __restrict__ w0,
                                              const float* __restrict__ w1,
                                              const float* __restrict__ w2,
                                              const float* __restrict__ w3,
                                              float* __restrict__ o) {
    int i = blockIdx.x * 256 + threadIdx.x;
    float v;
    if (i < 196608)       v = w0[i];
    else if (i < 262144)  v = w1[i - 196608];
    else if (i < 524288)  v = w2[i - 262144];
    else                  v = w3[i - 524288];
    o[i] = rtf(v);
}

// ---------------- copy + LayerNorm (block0 LN1): reads X, writes xg and tf32 xn ----------------
__global__ __launch_bounds__(256) void ln_copy_k(const float* __restrict__ x,
                                                 const float* __restrict__ g,
                                                 const float* __restrict__ b,
                                                 float* __restrict__ xg,
                                                 float* __restrict__ xn) {
    __shared__ float red[8];
    int row = blockIdx.x, tid = threadIdx.x;
    float v = x[(size_t)row * DIMC + tid];
    xg[(size_t)row * DIMC + tid] = v;

    float s = v;
#pragma unroll
    for (int o = 16; o > 0; o >>= 1) s += __shfl_xor_sync(0xffffffffu, s, o);
    if ((tid & 31) == 0) red[tid >> 5] = s;
    __syncthreads();
    float tot = 0.f;
#pragma unroll
    for (int i = 0; i < 8; i++) tot += red[i];
    float mu = tot * (1.f / 256.f);

    float d = v - mu;
    float s2 = d * d;
#pragma unroll
    for (int o = 16; o > 0; o >>= 1) s2 += __shfl_xor_sync(0xffffffffu, s2, o);
    __syncthreads();
    if ((tid & 31) == 0) red[tid >> 5] = s2;
    __syncthreads();
    float var = 0.f;
#pragma unroll
    for (int i = 0; i < 8; i++) var += red[i];
    var *= (1.f / 256.f);

    xn[(size_t)row * DIMC + tid] = rtf(d * rsqrtf(var + 1e-5f) * g[tid] + b[tid]);
}

// ---------------- tf32 GEMM: 128x256 block, cp.async 4-stage, BK=16 ----------------
// MODE 0: A gathered via srcmap; C = A@B+bias                      (qkv)
// MODE 1: C scattered via srcmap, +=; fused LN -> XN               (proj + LN2)
// MODE 2: C = tf32round(gelu(A@B+bias))                            (fc1)
// MODE 3: C = R + (A@B+bias); optional fused LN -> XN              (fc2 [+ next LN1])
template <int MODE>
__global__ __launch_bounds__(256, 1) void tgemm(const float* __restrict__ A,
                                                const float* __restrict__ B,
                                                const float* __restrict__ bias,
                                                float* __restrict__ C,
                                                const float* __restrict__ R,
                                                const float* __restrict__ gamma,
                                                const float* __restrict__ beta,
                                                float* __restrict__ XN,
                                                int K, int N, int shift) {
    extern __shared__ float sm[];

    int tid = threadIdx.x;
    int lane = tid & 31, wid = tid >> 5;
    int wm = wid >> 2, wn = wid & 3;
    int g = lane >> 2, tig = lane & 3;
    int bm = blockIdx.y << 7, bn = blockIdx.x << 8;

    // ---- cp.async staging maps ----
    int arow0 = tid >> 2, ac = (tid & 3) << 2;
    int gr0 = (MODE == 0) ? srcmap(bm + arow0, shift) : (bm + arow0);
    int gr1 = (MODE == 0) ? srcmap(bm + arow0 + 64, shift) : (bm + arow0 + 64);
    const float* aptr0 = A + (size_t)gr0 * K + ac;
    const float* aptr1 = A + (size_t)gr1 * K + ac;
    int asd0 = arow0 * A_STRIDE + ac;
    int asd1 = (arow0 + 64) * A_STRIDE + ac;
    int brow = tid >> 6, bc = (tid & 63) << 2;
    const float* bptr = B + (size_t)brow * N + bn + bc;
    int bsd = brow * B_STRIDE + bc;

    float acc[4][8][4];
#pragma unroll
    for (int mi = 0; mi < 4; mi++)
#pragma unroll
        for (int ni = 0; ni < 8; ni++)
#pragma unroll
            for (int e = 0; e < 4; e++) acc[mi][ni][e] = 0.f;

    const int NC = K >> 4;

#define ISSUE(slot, kc)                                                           \
    {                                                                             \
        float* d = sm + (slot) * SSZ;                                             \
        int k0 = (kc) << 4;                                                       \
        cpa16(d + asd0, aptr0 + k0);                                              \
        cpa16(d + asd1, aptr1 + k0);                                              \
        float* bd = d + ASZ;                                                      \
        const float* bs_ = bptr + (size_t)k0 * N;                                 \
        cpa16(bd + bsd,                bs_);                                      \
        cpa16(bd + bsd + 4 * B_STRIDE, bs_ + (size_t)4 * N);                      \
        cpa16(bd + bsd + 8 * B_STRIDE, bs_ + (size_t)8 * N);                      \
        cpa16(bd + bsd + 12 * B_STRIDE, bs_ + (size_t)12 * N);                    \
    }

#pragma unroll
    for (int s = 0; s < STAGES - 1; s++) {
        ISSUE(s, s);
        cp_commit();
    }

    for (int c = 0; c < NC; c++) {
        cp_wait<STAGES - 2>();
        __syncthreads();

        if (c + STAGES - 1 < NC) ISSUE((c + STAGES - 1) & (STAGES - 1), c + STAGES - 1);
        cp_commit();

        const unsigned* as = (const unsigned*)(sm + (c & (STAGES - 1)) * SSZ);
        const unsigned* bs = as + ASZ;
#pragma unroll
        for (int s8 = 0; s8 < 2; s8++) {
            int kb = s8 << 3;
            unsigned af[4][4], bf[8][2];
#pragma unroll
            for (int mi = 0; mi < 4; mi++) {
                int r0 = (wm * 64 + mi * 16 + g) * A_STRIDE + kb;
                af[mi][0] = as[r0 + tig];
                af[mi][1] = as[r0 + 8 * A_STRIDE + tig];
                af[mi][2] = as[r0 + tig + 4];
                af[mi][3] = as[r0 + 8 * A_STRIDE + tig + 4];
            }
#pragma unroll
            for (int ni = 0; ni < 8; ni++) {
                int cix = wn * 64 + ni * 8 + g;
                bf[ni][0] = bs[(kb + tig) * B_STRIDE + cix];
                bf[ni][1] = bs[(kb + tig + 4) * B_STRIDE + cix];
            }
#pragma unroll
            for (int mi = 0; mi < 4; mi++)
#pragma unroll
                for (int ni = 0; ni < 8; ni++) mma_tf32(acc[mi][ni], af[mi], bf[ni]);
        }
    }
#undef ISSUE

    // ---- epilogue ----
    if constexpr (MODE == 0 || MODE == 2) {
#pragma unroll
        for (int mi = 0; mi < 4; mi++) {
            int r0 = bm + wm * 64 + mi * 16 + g;
            int r1 = r0 + 8;
#pragma unroll
            for (int ni = 0; ni < 8; ni++) {
                int col = bn + wn * 64 + ni * 8 + (tig << 1);
                float bv0 = bias[col], bv1 = bias[col + 1];
                float v00 = acc[mi][ni][0] + bv0, v01 = acc[mi][ni][1] + bv1;
                float v10 = acc[mi][ni][2] + bv0, v11 = acc[mi][ni][3] + bv1;
                size_t o0 = (size_t)r0 * N + col;
                size_t o1 = (size_t)r1 * N + col;
                if constexpr (MODE == 0) {
                    *(float2*)&C[o0] = make_float2(v00, v01);
                    *(float2*)&C[o1] = make_float2(v10, v11);
                } else {
                    const float is2 = 0.70710678118654752f;
                    *(float2*)&C[o0] = make_float2(rtf(0.5f * v00 * (1.f + erff(v00 * is2))),
                                                   rtf(0.5f * v01 * (1.f + erff(v01 * is2))));
                    *(float2*)&C[o1] = make_float2(rtf(0.5f * v10 * (1.f + erff(v10 * is2))),
                                                   rtf(0.5f * v11 * (1.f + erff(v11 * is2))));
                }
            }
        }
    } else {
        // MODE 1 / MODE 3: residual add (+scatter for MODE 1), optional fused LN.
        // N == 256 here, so the full output row lives inside this CTA (bn == 0).
        bool fuse = (gamma != nullptr);
        float psum0[4], psq0[4], psum1[4], psq1[4];

#pragma unroll
        for (int mi = 0; mi < 4; mi++) {
            int r0 = bm + wm * 64 + mi * 16 + g;
            int r1 = r0 + 8;
            int d0 = (MODE == 1) ? srcmap(r0, shift) : r0;
            int d1 = (MODE == 1) ? srcmap(r1, shift) : r1;
            float s0 = 0.f, q0 = 0.f, s1 = 0.f, q1 = 0.f;
#pragma unroll
            for (int ni = 0; ni < 8; ni++) {
                int col = bn + wn * 64 + ni * 8 + (tig << 1);
                float bv0 = bias[col], bv1 = bias[col + 1];
                float v00 = acc[mi][ni][0] + bv0, v01 = acc[mi][ni][1] + bv1;
                float v10 = acc[mi][ni][2] + bv0, v11 = acc[mi][ni][3] + bv1;
                size_t o0 = (size_t)d0 * N + col;
                size_t o1 = (size_t)d1 * N + col;
                if constexpr (MODE == 1) {
                    float2 p0 = *(const float2*)&C[o0];
                    float2 p1 = *(const float2*)&C[o1];
                    v00 += p0.x; v01 += p0.y; v10 += p1.x; v11 += p1.y;
                } else {
                    float2 p0 = *(const float2*)&R[o0];
                    float2 p1 = *(const float2*)&R[o1];
                    v00 += p0.x; v01 += p0.y; v10 += p1.x; v11 += p1.y;
                }
                *(float2*)&C[o0] = make_float2(v00, v01);
                *(float2*)&C[o1] = make_float2(v10, v11);
                acc[mi][ni][0] = v00; acc[mi][ni][1] = v01;
                acc[mi][ni][2] = v10; acc[mi][ni][3] = v11;
                s0 += v00 + v01; q0 = fmaf(v00, v00, fmaf(v01, v01, q0));
                s1 += v10 + v11; q1 = fmaf(v10, v10, fmaf(v11, v11, q1));
            }
            psum0[mi] = s0; psq0[mi] = q0; psum1[mi] = s1; psq1[mi] = q1;
        }

        if (fuse) {
            float* s_sum = sm;          // [128*4]
            float* s_sq  = sm + 512;    // [128*4]
            float* s_mu  = sm + 1024;   // [128]
            float* s_rs  = sm + 1152;   // [128]

            // reduce over tig within warp
#pragma unroll
            for (int mi = 0; mi < 4; mi++) {
                psum0[mi] += __shfl_xor_sync(0xffffffffu, psum0[mi], 1);
                psum0[mi] += __shfl_xor_sync(0xffffffffu, psum0[mi], 2);
                psq0[mi]  += __shfl_xor_sync(0xffffffffu, psq0[mi], 1);
                psq0[mi]  += __shfl_xor_sync(0xffffffffu, psq0[mi], 2);
                psum1[mi] += __shfl_xor_sync(0xffffffffu, psum1[mi], 1);
                psum1[mi] += __shfl_xor_sync(0xffffffffu, psum1[mi], 2);
                psq1[mi]  += __shfl_xor_sync(0xffffffffu, psq1[mi], 1);
                psq1[mi]  += __shfl_xor_sync(0xffffffffu, psq1[mi], 2);
            }

            __syncthreads();   // all warps done reading mainloop smem
            if (tig == 0) {
#pragma unroll
                for (int mi = 0; mi < 4; mi++) {
                    int lr0 = wm * 64 + mi * 16 + g;
                    int lr1 = lr0 + 8;
                    s_sum[lr0 * 4 + wn] = psum0[mi];
                    s_sq [lr0 * 4 + wn] = psq0[mi];
                    s_sum[lr1 * 4 + wn] = psum1[mi];
                    s_sq [lr1 * 4 + wn] = psq1[mi];
                }
            }
            __syncthreads();
            if (tid < 128) {
                float su = s_sum[tid * 4] + s_sum[tid * 4 + 1] + s_sum[tid * 4 + 2] + s_sum[tid * 4 + 3];
                float sq = s_sq[tid * 4] + s_sq[tid * 4 + 1] + s_sq[tid * 4 + 2] + s_sq[tid * 4 + 3];
                float mu = su * (1.f / 256.f);
                float var = sq * (1.f / 256.f) - mu * mu;
                s_mu[tid] = mu;
                s_rs[tid] = rsqrtf(var + 1e-5f);
            }
            __syncthreads();

#pragma unroll
            for (int mi = 0; mi < 4; mi++) {
                int lr0 = wm * 64 + mi * 16 + g;
                int lr1 = lr0 + 8;
                int r0 = bm + lr0, r1 = bm + lr1;
                int d0 = (MODE == 1) ? srcmap(r0, shift) : r0;
                int d1 = (MODE == 1) ? srcmap(r1, shift) : r1;
                float mu0 = s_mu[lr0], rs0 = s_rs[lr0];
                float mu1 = s_mu[lr1], rs1 = s_rs[lr1];
#pragma unroll
                for (int ni = 0; ni < 8; ni++) {
                    int col = bn + wn * 64 + ni * 8 + (tig << 1);
                    float ga0 = gamma[col], ga1 = gamma[col + 1];
                    float be0 = beta[col],  be1 = beta[col + 1];
                    size_t o0 = (size_t)d0 * DIMC + col;
                    size_t o1 = (size_t)d1 * DIMC + col;
                    *(float2*)&XN[o0] = make_float2(
                        rtf((acc[mi][ni][0] - mu0) * rs0 * ga0 + be0),
                        rtf((acc[mi][ni][1] - mu0) * rs0 * ga1 + be1));
                    *(float2*)&XN[o1] = make_float2(
                        rtf((acc[mi][ni][2] - mu1) * rs1 * ga0 + be0),
                        rtf((acc[mi][ni][3] - mu1) * rs1 * ga1 + be1));
                }
            }
        }
    }
}

// ---------------- Windowed attention (parallel softmax, tf32-rounded output) ----------------
__global__ __launch_bounds__(256) void attn_k(const float* __restrict__ qkv,
                                              const float* __restrict__ rpb,
                                              float* __restrict__ out,
                                              int shifted) {
    __shared__ float Qs[64][33], Ks[64][33], Vs[64][33];
    __shared__ float S[64][65];

    int w = blockIdx.x >> 3, h = blockIdx.x & 7;
    int tid = threadIdx.x;
    const float scale = 0.17677669529663687f;

    size_t base = (size_t)w * 64 * QKVN;
    for (int e = tid; e < 2048; e += 256) {
        int i = e >> 5, d = e & 31;
        size_t ro = base + (size_t)i * QKVN + h * 32 + d;
        Qs[i][d] = qkv[ro] * scale;
        Ks[i][d] = qkv[ro + 256];
        Vs[i][d] = qkv[ro + 512];
    }
    __syncthreads();

    int wh = (w & 63) >> 3, ww = w & 7;
    for (int e = tid; e < 4096; e += 256) {
        int i = e >> 6, j = e & 63;
        float s = 0.f;
#pragma unroll
        for (int d = 0; d < 32; d++) s = fmaf(Qs[i][d], Ks[j][d], s);
        int ri = i >> 3, ci = i & 7, rj = j >> 3, cj = j & 7;
        int idx = (ri - rj + 7) * 15 + (ci - cj + 7);
        s += rpb[idx * 8 + h];
        if (shifted) {
            int li = ((wh == 7) ? (ri < 4 ? 1 : 2) : 0) * 3 + ((ww == 7) ? (ci < 4 ? 1 : 2) : 0);
            int lj = ((wh == 7) ? (rj < 4 ? 1 : 2) : 0) * 3 + ((ww == 7) ? (cj < 4 ? 1 : 2) : 0);
            if (li != lj) s -= 100.0f;
        }
        S[i][j] = s;
    }
    __syncthreads();

    // parallel softmax: 4 threads per row
    {
        int r = tid >> 2, q = (tid & 3) << 4;
        float m = -1e30f;
#pragma unroll
        for (int jj = 0; jj < 16; jj++) m = fmaxf(m, S[r][q + jj]);
        m = fmaxf(m, __shfl_xor_sync(0xffffffffu, m, 1));
        m = fmaxf(m, __shfl_xor_sync(0xffffffffu, m, 2));
        float sum = 0.f;
#pragma unroll
        for (int jj = 0; jj < 16; jj++) {
            float e = expf(S[r][q + jj] - m);
            S[r][q + jj] = e;
            sum += e;
        }
        sum += __shfl_xor_sync(0xffffffffu, sum, 1);
        sum += __shfl_xor_sync(0xffffffffu, sum, 2);
        float inv = 1.f / sum;
#pragma unroll
        for (int jj = 0; jj < 16; jj++) S[r][q + jj] *= inv;
    }
    __syncthreads();

    for (int e = tid; e < 2048; e += 256) {
        int i = e >> 5, d = e & 31;
        float o = 0.f;
#pragma unroll
        for (int j = 0; j < 64; j++) o = fmaf(S[i][j], Vs[j][d], o);
        out[(size_t)(w * 64 + i) * DIMC + h * 32 + d] = rtf(o);
    }
}

// ---------------- launch ----------------
extern "C" void kernel_launch(void* const* d_in, const int* in_sizes, int n_in,
                              void* d_out, int out_size) {
    float *xg, *xn, *qkvb, *attnb, *hb, *wb;
    cudaGetSymbolAddress((void**)&xg, g_x);
    cudaGetSymbolAddress((void**)&xn, g_xn);
    cudaGetSymbolAddress((void**)&qkvb, g_qkv);
    cudaGetSymbolAddress((void**)&attnb, g_attn);
    cudaGetSymbolAddress((void**)&hb, g_h);
    cudaGetSymbolAddress((void**)&wb, g_w);

    cudaFuncSetAttribute(tgemm<0>, cudaFuncAttributeMaxDynamicSharedMemorySize, SMEM_BYTES);
    cudaFuncSetAttribute(tgemm<1>, cudaFuncAttributeMaxDynamicSharedMemorySize, SMEM_BYTES);
    cudaFuncSetAttribute(tgemm<2>, cudaFuncAttributeMaxDynamicSharedMemorySize, SMEM_BYTES);
    cudaFuncSetAttribute(tgemm<3>, cudaFuncAttributeMaxDynamicSharedMemorySize, SMEM_BYTES);

    const float* X = (const float*)d_in[0];
    const int WOFF_P = 196608, WOFF_F1 = 262144, WOFF_F2 = 524288, WSZ = 786432;

    // tf32 weight prepass: 2 launches total
    for (int blk = 0; blk < 2; blk++) {
        const float* const* P = (const float* const*)(d_in + 1 + blk * 13);
        cvt4_k<<<786432 / 256, 256>>>(P[2], P[5], P[9], P[11], wb + blk * WSZ);
    }

    for (int blk = 0; blk < 2; blk++) {
        const float* const* P = (const float* const*)(d_in + 1 + blk * 13);
        const float *qkvbias = P[3], *rpb = P[4];
        const float *pb = P[6], *n2g = P[7], *n2b = P[8];
        const float *f1b = P[10], *f2b = P[12];
        const float* W = wb + blk * WSZ;
        int shift = blk ? 4 : 0;

        if (blk == 0) {
            // copy + LN1 fused (reads pristine input X)
            ln_copy_k<<<TOK, 256>>>(X, P[0], P[1], xg, xn);
        }
        // (blk1's LN1 was fused into blk0's fc2 epilogue)

        tgemm<0><<<dim3(QKVN / 256, TOK / 128), 256, SMEM_BYTES>>>(
            xn, W, qkvbias, qkvb, nullptr, nullptr, nullptr, nullptr, DIMC, QKVN, shift);
        attn_k<<<8192, 256>>>(qkvb, rpb, attnb, blk);
        // proj + residual + fused LN2 -> xn
        tgemm<1><<<dim3(DIMC / 256, TOK / 128), 256, SMEM_BYTES>>>(
            attnb, W + WOFF_P, pb, xg, nullptr, n2g, n2b, xn, DIMC, DIMC, shift);
        tgemm<2><<<dim3(MLPH / 256, TOK / 128), 256, SMEM_BYTES>>>(
            xn, W + WOFF_F1, f1b, hb, nullptr, nullptr, nullptr, nullptr, DIMC, MLPH, 0);
        if (blk == 0) {
            // fc2 + residual into xg, fused LN1-of-block1 -> xn
            const float* const* P1 = (const float* const*)(d_in + 1 + 13);
            tgemm<3><<<dim3(DIMC / 256, TOK / 128), 256, SMEM_BYTES>>>(
                hb, W + WOFF_F2, f2b, xg, xg, P1[0], P1[1], xn, MLPH, DIMC, 0);
        } else {
            // final fc2 + residual straight to d_out (no LN)
            tgemm<3><<<dim3(DIMC / 256, TOK / 128), 256, SMEM_BYTES>>>(
                hb, W + WOFF_F2, f2b, (float*)d_out, xg, nullptr, nullptr, nullptr, MLPH, DIMC, 0);
        }
    }
}

// round 15
// speedup vs baseline: 2.8593x; 1.2029x over previous
#include <cuda_runtime.h>
#include <math.h>

#define TOK   65536          // B * H * W
#define DIMC  256
#define QKVN  768
#define MLPH  1024

#define STAGES 4
#define BK     16
#define A_STRIDE 20          // 16 k + 4 pad (floats)
#define B_STRIDE 264         // 256 n + 8 pad (floats)
#define ASZ (128 * A_STRIDE)
#define BSZ (BK * B_STRIDE)
#define SSZ (ASZ + BSZ)
#define SMEM_BYTES (STAGES * SSZ * 4)

// ---------------- scratch (static device globals; no allocation) ----------------
__device__ float g_x   [TOK * DIMC];
__device__ float g_xn  [TOK * DIMC];
__device__ float g_qkv [TOK * QKVN];
__device__ float g_attn[TOK * DIMC];
__device__ float g_h   [TOK * MLPH];
__device__ float g_w   [2][786432];   // tf32-rounded weights per block: qkvw|pw|f1w|f2w

__device__ __forceinline__ int srcmap(int m, int shift) {
    int w = m >> 6, n = m & 63;
    int b = w >> 6, widx = w & 63;
    int wh = widx >> 3, ww = widx & 7;
    int gr = ((wh << 3) + (n >> 3) + shift) & 63;
    int gc = ((ww << 3) + (n & 7) + shift) & 63;
    return (((b << 6) | gr) << 6) | gc;
}

__device__ __forceinline__ unsigned f2tf(float f) {
    unsigned u;
    asm("cvt.rna.tf32.f32 %0, %1;" : "=r"(u) : "f"(f));
    return u;
}
__device__ __forceinline__ float rtf(float f) { return __uint_as_float(f2tf(f)); }

__device__ __forceinline__ void mma_tf32(float c[4], const unsigned a[4], const unsigned b[2]) {
    asm volatile(
        "mma.sync.aligned.m16n8k8.row.col.f32.tf32.tf32.f32 "
        "{%0,%1,%2,%3}, {%4,%5,%6,%7}, {%8,%9}, {%0,%1,%2,%3};\n"
        : "+f"(c[0]), "+f"(c[1]), "+f"(c[2]), "+f"(c[3])
        : "r"(a[0]), "r"(a[1]), "r"(a[2]), "r"(a[3]), "r"(b[0]), "r"(b[1]));
}

__device__ __forceinline__ void cpa16(float* dst, const float* src) {
    unsigned d = (unsigned)__cvta_generic_to_shared(dst);
    asm volatile("cp.async.cg.shared.global [%0], [%1], 16;\n" :: "r"(d), "l"(src));
}
__device__ __forceinline__ void cp_commit() { asm volatile("cp.async.commit_group;\n" ::: "memory"); }
template <int N> __device__ __forceinline__ void cp_wait() {
    asm volatile("cp.async.wait_group %0;\n" :: "n"(N) : "memory");
}

// ---------------- weight -> tf32 rounding (4 tensors in one launch) ----------------
__global__ __launch_bounds__(256) void cvt4_k(const float* __restrict__ w0,
                                              const float* __restrict__ w1,
                                              const float* __restrict__ w2,
                                              const float* __restrict__ w3,
                                              float* __restrict__ o) {
    int i = blockIdx.x * 256 + threadIdx.x;
    float v;
    if (i < 196608)       v = w0[i];
    else if (i < 262144)  v = w1[i - 196608];
    else if (i < 524288)  v = w2[i - 262144];
    else                  v = w3[i - 524288];
    o[i] = rtf(v);
}

// ---------------- copy + LayerNorm (block0 LN1) ----------------
__global__ __launch_bounds__(256) void ln_copy_k(const float* __restrict__ x,
                                                 const float* __restrict__ g,
                                                 const float* __restrict__ b,
                                                 float* __restrict__ xg,
                                                 float* __restrict__ xn) {
    __shared__ float red[8];
    int row = blockIdx.x, tid = threadIdx.x;
    float v = x[(size_t)row * DIMC + tid];
    xg[(size_t)row * DIMC + tid] = v;

    float s = v;
#pragma unroll
    for (int o = 16; o > 0; o >>= 1) s += __shfl_xor_sync(0xffffffffu, s, o);
    if ((tid & 31) == 0) red[tid >> 5] = s;
    __syncthreads();
    float tot = 0.f;
#pragma unroll
    for (int i = 0; i < 8; i++) tot += red[i];
    float mu = tot * (1.f / 256.f);

    float d = v - mu;
    float s2 = d * d;
#pragma unroll
    for (int o = 16; o > 0; o >>= 1) s2 += __shfl_xor_sync(0xffffffffu, s2, o);
    __syncthreads();
    if ((tid & 31) == 0) red[tid >> 5] = s2;
    __syncthreads();
    float var = 0.f;
#pragma unroll
    for (int i = 0; i < 8; i++) var += red[i];
    var *= (1.f / 256.f);

    xn[(size_t)row * DIMC + tid] = rtf(d * rsqrtf(var + 1e-5f) * g[tid] + b[tid]);
}

// ---------------- tf32 GEMM: 128x256 block, cp.async 4-stage, BK=16 ----------------
template <int MODE>
__global__ __launch_bounds__(256, 1) void tgemm(const float* __restrict__ A,
                                                const float* __restrict__ B,
                                                const float* __restrict__ bias,
                                                float* __restrict__ C,
                                                const float* __restrict__ R,
                                                const float* __restrict__ gamma,
                                                const float* __restrict__ beta,
                                                float* __restrict__ XN,
                                                int K, int N, int shift) {
    extern __shared__ float sm[];

    int tid = threadIdx.x;
    int lane = tid & 31, wid = tid >> 5;
    int wm = wid >> 2, wn = wid & 3;
    int g = lane >> 2, tig = lane & 3;
    int bm = blockIdx.y << 7, bn = blockIdx.x << 8;

    int arow0 = tid >> 2, ac = (tid & 3) << 2;
    int gr0 = (MODE == 0) ? srcmap(bm + arow0, shift) : (bm + arow0);
    int gr1 = (MODE == 0) ? srcmap(bm + arow0 + 64, shift) : (bm + arow0 + 64);
    const float* aptr0 = A + (size_t)gr0 * K + ac;
    const float* aptr1 = A + (size_t)gr1 * K + ac;
    int asd0 = arow0 * A_STRIDE + ac;
    int asd1 = (arow0 + 64) * A_STRIDE + ac;
    int brow = tid >> 6, bc = (tid & 63) << 2;
    const float* bptr = B + (size_t)brow * N + bn + bc;
    int bsd = brow * B_STRIDE + bc;

    float acc[4][8][4];
#pragma unroll
    for (int mi = 0; mi < 4; mi++)
#pragma unroll
        for (int ni = 0; ni < 8; ni++)
#pragma unroll
            for (int e = 0; e < 4; e++) acc[mi][ni][e] = 0.f;

    const int NC = K >> 4;

#define ISSUE(slot, kc)                                                           \
    {                                                                             \
        float* d = sm + (slot) * SSZ;                                             \
        int k0 = (kc) << 4;                                                       \
        cpa16(d + asd0, aptr0 + k0);                                              \
        cpa16(d + asd1, aptr1 + k0);                                              \
        float* bd = d + ASZ;                                                      \
        const float* bs_ = bptr + (size_t)k0 * N;                                 \
        cpa16(bd + bsd,                bs_);                                      \
        cpa16(bd + bsd + 4 * B_STRIDE, bs_ + (size_t)4 * N);                      \
        cpa16(bd + bsd + 8 * B_STRIDE, bs_ + (size_t)8 * N);                      \
        cpa16(bd + bsd + 12 * B_STRIDE, bs_ + (size_t)12 * N);                    \
    }

#pragma unroll
    for (int s = 0; s < STAGES - 1; s++) {
        ISSUE(s, s);
        cp_commit();
    }

    for (int c = 0; c < NC; c++) {
        cp_wait<STAGES - 2>();
        __syncthreads();

        if (c + STAGES - 1 < NC) ISSUE((c + STAGES - 1) & (STAGES - 1), c + STAGES - 1);
        cp_commit();

        const unsigned* as = (const unsigned*)(sm + (c & (STAGES - 1)) * SSZ);
        const unsigned* bs = as + ASZ;
#pragma unroll
        for (int s8 = 0; s8 < 2; s8++) {
            int kb = s8 << 3;
            unsigned af[4][4], bf[8][2];
#pragma unroll
            for (int mi = 0; mi < 4; mi++) {
                int r0 = (wm * 64 + mi * 16 + g) * A_STRIDE + kb;
                af[mi][0] = as[r0 + tig];
                af[mi][1] = as[r0 + 8 * A_STRIDE + tig];
                af[mi][2] = as[r0 + tig + 4];
                af[mi][3] = as[r0 + 8 * A_STRIDE + tig + 4];
            }
#pragma unroll
            for (int ni = 0; ni < 8; ni++) {
                int cix = wn * 64 + ni * 8 + g;
                bf[ni][0] = bs[(kb + tig) * B_STRIDE + cix];
                bf[ni][1] = bs[(kb + tig + 4) * B_STRIDE + cix];
            }
#pragma unroll
            for (int mi = 0; mi < 4; mi++)
#pragma unroll
                for (int ni = 0; ni < 8; ni++) mma_tf32(acc[mi][ni], af[mi], bf[ni]);
        }
    }
#undef ISSUE

    // ---- epilogue ----
    if constexpr (MODE == 0 || MODE == 2) {
#pragma unroll
        for (int mi = 0; mi < 4; mi++) {
            int r0 = bm + wm * 64 + mi * 16 + g;
            int r1 = r0 + 8;
#pragma unroll
            for (int ni = 0; ni < 8; ni++) {
                int col = bn + wn * 64 + ni * 8 + (tig << 1);
                float bv0 = bias[col], bv1 = bias[col + 1];
                float v00 = acc[mi][ni][0] + bv0, v01 = acc[mi][ni][1] + bv1;
                float v10 = acc[mi][ni][2] + bv0, v11 = acc[mi][ni][3] + bv1;
                size_t o0 = (size_t)r0 * N + col;
                size_t o1 = (size_t)r1 * N + col;
                if constexpr (MODE == 0) {
                    *(float2*)&C[o0] = make_float2(rtf(v00), rtf(v01));
                    *(float2*)&C[o1] = make_float2(rtf(v10), rtf(v11));
                } else {
                    const float is2 = 0.70710678118654752f;
                    *(float2*)&C[o0] = make_float2(rtf(0.5f * v00 * (1.f + erff(v00 * is2))),
                                                   rtf(0.5f * v01 * (1.f + erff(v01 * is2))));
                    *(float2*)&C[o1] = make_float2(rtf(0.5f * v10 * (1.f + erff(v10 * is2))),
                                                   rtf(0.5f * v11 * (1.f + erff(v11 * is2))));
                }
            }
        }
    } else {
        bool fuse = (gamma != nullptr);
        float psum0[4], psq0[4], psum1[4], psq1[4];

#pragma unroll
        for (int mi = 0; mi < 4; mi++) {
            int r0 = bm + wm * 64 + mi * 16 + g;
            int r1 = r0 + 8;
            int d0 = (MODE == 1) ? srcmap(r0, shift) : r0;
            int d1 = (MODE == 1) ? srcmap(r1, shift) : r1;
            float s0 = 0.f, q0 = 0.f, s1 = 0.f, q1 = 0.f;
#pragma unroll
            for (int ni = 0; ni < 8; ni++) {
                int col = bn + wn * 64 + ni * 8 + (tig << 1);
                float bv0 = bias[col], bv1 = bias[col + 1];
                float v00 = acc[mi][ni][0] + bv0, v01 = acc[mi][ni][1] + bv1;
                float v10 = acc[mi][ni][2] + bv0, v11 = acc[mi][ni][3] + bv1;
                size_t o0 = (size_t)d0 * N + col;
                size_t o1 = (size_t)d1 * N + col;
                if constexpr (MODE == 1) {
                    float2 p0 = *(const float2*)&C[o0];
                    float2 p1 = *(const float2*)&C[o1];
                    v00 += p0.x; v01 += p0.y; v10 += p1.x; v11 += p1.y;
                } else {
                    float2 p0 = *(const float2*)&R[o0];
                    float2 p1 = *(const float2*)&R[o1];
                    v00 += p0.x; v01 += p0.y; v10 += p1.x; v11 += p1.y;
                }
                *(float2*)&C[o0] = make_float2(v00, v01);
                *(float2*)&C[o1] = make_float2(v10, v11);
                acc[mi][ni][0] = v00; acc[mi][ni][1] = v01;
                acc[mi][ni][2] = v10; acc[mi][ni][3] = v11;
                s0 += v00 + v01; q0 = fmaf(v00, v00, fmaf(v01, v01, q0));
                s1 += v10 + v11; q1 = fmaf(v10, v10, fmaf(v11, v11, q1));
            }
            psum0[mi] = s0; psq0[mi] = q0; psum1[mi] = s1; psq1[mi] = q1;
        }

        if (fuse) {
            float* s_sum = sm;
            float* s_sq  = sm + 512;
            float* s_mu  = sm + 1024;
            float* s_rs  = sm + 1152;

#pragma unroll
            for (int mi = 0; mi < 4; mi++) {
                psum0[mi] += __shfl_xor_sync(0xffffffffu, psum0[mi], 1);
                psum0[mi] += __shfl_xor_sync(0xffffffffu, psum0[mi], 2);
                psq0[mi]  += __shfl_xor_sync(0xffffffffu, psq0[mi], 1);
                psq0[mi]  += __shfl_xor_sync(0xffffffffu, psq0[mi], 2);
                psum1[mi] += __shfl_xor_sync(0xffffffffu, psum1[mi], 1);
                psum1[mi] += __shfl_xor_sync(0xffffffffu, psum1[mi], 2);
                psq1[mi]  += __shfl_xor_sync(0xffffffffu, psq1[mi], 1);
                psq1[mi]  += __shfl_xor_sync(0xffffffffu, psq1[mi], 2);
            }

            __syncthreads();
            if (tig == 0) {
#pragma unroll
                for (int mi = 0; mi < 4; mi++) {
                    int lr0 = wm * 64 + mi * 16 + g;
                    int lr1 = lr0 + 8;
                    s_sum[lr0 * 4 + wn] = psum0[mi];
                    s_sq [lr0 * 4 + wn] = psq0[mi];
                    s_sum[lr1 * 4 + wn] = psum1[mi];
                    s_sq [lr1 * 4 + wn] = psq1[mi];
                }
            }
            __syncthreads();
            if (tid < 128) {
                float su = s_sum[tid * 4] + s_sum[tid * 4 + 1] + s_sum[tid * 4 + 2] + s_sum[tid * 4 + 3];
                float sq = s_sq[tid * 4] + s_sq[tid * 4 + 1] + s_sq[tid * 4 + 2] + s_sq[tid * 4 + 3];
                float mu = su * (1.f / 256.f);
                float var = sq * (1.f / 256.f) - mu * mu;
                s_mu[tid] = mu;
                s_rs[tid] = rsqrtf(var + 1e-5f);
            }
            __syncthreads();

#pragma unroll
            for (int mi = 0; mi < 4; mi++) {
                int lr0 = wm * 64 + mi * 16 + g;
                int lr1 = lr0 + 8;
                int r0 = bm + lr0, r1 = bm + lr1;
                int d0 = (MODE == 1) ? srcmap(r0, shift) : r0;
                int d1 = (MODE == 1) ? srcmap(r1, shift) : r1;
                float mu0 = s_mu[lr0], rs0 = s_rs[lr0];
                float mu1 = s_mu[lr1], rs1 = s_rs[lr1];
#pragma unroll
                for (int ni = 0; ni < 8; ni++) {
                    int col = bn + wn * 64 + ni * 8 + (tig << 1);
                    float ga0 = gamma[col], ga1 = gamma[col + 1];
                    float be0 = beta[col],  be1 = beta[col + 1];
                    size_t o0 = (size_t)d0 * DIMC + col;
                    size_t o1 = (size_t)d1 * DIMC + col;
                    *(float2*)&XN[o0] = make_float2(
                        rtf((acc[mi][ni][0] - mu0) * rs0 * ga0 + be0),
                        rtf((acc[mi][ni][1] - mu0) * rs0 * ga1 + be1));
                    *(float2*)&XN[o1] = make_float2(
                        rtf((acc[mi][ni][2] - mu1) * rs1 * ga0 + be0),
                        rtf((acc[mi][ni][3] - mu1) * rs1 * ga1 + be1));
                }
            }
        }
    }
}

// ---------------- Windowed attention: tensor-core QK^T and PV ----------------
// Qs/Ks stride 36 (bank=4r+c conflict-free), Vs stride 40 (bank=8r+c), S stride 68.
__global__ __launch_bounds__(256) void attn_k(const float* __restrict__ qkv,
                                              const float* __restrict__ rpb,
                                              float* __restrict__ out,
                                              int shifted) {
    __shared__ float Qs[64][36], Ks[64][36], Vs[64][40];
    __shared__ float S[64][68];

    int w = blockIdx.x >> 3, h = blockIdx.x & 7;
    int tid = threadIdx.x;
    int lane = tid & 31, wid = tid >> 5;
    int g = lane >> 2, tig = lane & 3;
    const float scale = 0.17677669529663687f;

    // stage Q (pre-scaled), K, V — tf32-rounded so mma truncation is exact
    size_t base = (size_t)w * 64 * QKVN;
    for (int e = tid; e < 2048; e += 256) {
        int i = e >> 5, d = e & 31;
        size_t ro = base + (size_t)i * QKVN + h * 32 + d;
        Qs[i][d] = rtf(qkv[ro] * scale);
        Ks[i][d] = rtf(qkv[ro + 256]);
        Vs[i][d] = rtf(qkv[ro + 512]);
    }
    __syncthreads();

    // ---- S = Q @ K^T via mma: warp covers 16 rows x 32 cols ----
    int wi = (wid >> 1) << 4;     // 0,16,32,48
    int wj = (wid & 1) << 5;      // 0,32
    {
        float sacc[4][4];
#pragma unroll
        for (int ni = 0; ni < 4; ni++)
#pragma unroll
            for (int e = 0; e < 4; e++) sacc[ni][e] = 0.f;

#pragma unroll
        for (int kk = 0; kk < 4; kk++) {
            int k0 = kk << 3;
            unsigned a[4], b[4][2];
            a[0] = __float_as_uint(Qs[wi + g][k0 + tig]);
            a[1] = __float_as_uint(Qs[wi + g + 8][k0 + tig]);
            a[2] = __float_as_uint(Qs[wi + g][k0 + tig + 4]);
            a[3] = __float_as_uint(Qs[wi + g + 8][k0 + tig + 4]);
#pragma unroll
            for (int ni = 0; ni < 4; ni++) {
                int n = wj + ni * 8 + g;
                b[ni][0] = __float_as_uint(Ks[n][k0 + tig]);
                b[ni][1] = __float_as_uint(Ks[n][k0 + tig + 4]);
            }
#pragma unroll
            for (int ni = 0; ni < 4; ni++) mma_tf32(sacc[ni], a, b[ni]);
        }

        // add rel-pos bias (+shift mask), store S
        int wh = (w & 63) >> 3, ww = w & 7;
        int i0 = wi + g, i1 = i0 + 8;
        int ri0 = i0 >> 3, ci0 = i0 & 7, ri1 = i1 >> 3, ci1 = i1 & 7;
        int li0 = 0, li1 = 0;
        if (shifted) {
            li0 = ((wh == 7) ? (ri0 < 4 ? 1 : 2) : 0) * 3 + ((ww == 7) ? (ci0 < 4 ? 1 : 2) : 0);
            li1 = ((wh == 7) ? (ri1 < 4 ? 1 : 2) : 0) * 3 + ((ww == 7) ? (ci1 < 4 ? 1 : 2) : 0);
        }
#pragma unroll
        for (int ni = 0; ni < 4; ni++) {
            int j0 = wj + ni * 8 + (tig << 1);
#pragma unroll
            for (int jj = 0; jj < 2; jj++) {
                int j = j0 + jj;
                int rj = j >> 3, cj = j & 7;
                int idx = ((ri0 - rj + 7) * 15 + (ci0 - cj + 7)) * 8 + h;
                float b0 = rpb[idx];
                int idx1 = ((ri1 - rj + 7) * 15 + (ci1 - cj + 7)) * 8 + h;
                float b1 = rpb[idx1];
                if (shifted) {
                    int lj = ((wh == 7) ? (rj < 4 ? 1 : 2) : 0) * 3 + ((ww == 7) ? (cj < 4 ? 1 : 2) : 0);
                    if (li0 != lj) b0 -= 100.0f;
                    if (li1 != lj) b1 -= 100.0f;
                }
                S[i0][j] = sacc[ni][jj] + b0;
                S[i1][j] = sacc[ni][2 + jj] + b1;
            }
        }
    }
    __syncthreads();

    // ---- softmax: 4 threads per row; write tf32-rounded P ----
    {
        int r = tid >> 2, q = (tid & 3) << 4;
        float m = -1e30f;
#pragma unroll
        for (int jj = 0; jj < 16; jj++) m = fmaxf(m, S[r][q + jj]);
        m = fmaxf(m, __shfl_xor_sync(0xffffffffu, m, 1));
        m = fmaxf(m, __shfl_xor_sync(0xffffffffu, m, 2));
        float sum = 0.f;
        float ev[16];
#pragma unroll
        for (int jj = 0; jj < 16; jj++) {
            ev[jj] = expf(S[r][q + jj] - m);
            sum += ev[jj];
        }
        sum += __shfl_xor_sync(0xffffffffu, sum, 1);
        sum += __shfl_xor_sync(0xffffffffu, sum, 2);
        float inv = 1.f / sum;
#pragma unroll
        for (int jj = 0; jj < 16; jj++) S[r][q + jj] = rtf(ev[jj] * inv);
    }
    __syncthreads();

    // ---- O = P @ V via mma: warp covers 16 rows x 16 cols ----
    {
        int wi2 = (wid >> 1) << 4;
        int wd = (wid & 1) << 4;     // 0 or 16
        float oacc[2][4];
#pragma unroll
        for (int ni = 0; ni < 2; ni++)
#pragma unroll
            for (int e = 0; e < 4; e++) oacc[ni][e] = 0.f;

#pragma unroll
        for (int kk = 0; kk < 8; kk++) {
            int k0 = kk << 3;
            unsigned a[4], b[2][2];
            a[0] = __float_as_uint(S[wi2 + g][k0 + tig]);
            a[1] = __float_as_uint(S[wi2 + g + 8][k0 + tig]);
            a[2] = __float_as_uint(S[wi2 + g][k0 + tig + 4]);
            a[3] = __float_as_uint(S[wi2 + g + 8][k0 + tig + 4]);
#pragma unroll
            for (int ni = 0; ni < 2; ni++) {
                int n = wd + ni * 8 + g;
                b[ni][0] = __float_as_uint(Vs[k0 + tig][n]);
                b[ni][1] = __float_as_uint(Vs[k0 + tig + 4][n]);
            }
#pragma unroll
            for (int ni = 0; ni < 2; ni++) mma_tf32(oacc[ni], a, b[ni]);
        }

        int i0 = wi2 + g, i1 = i0 + 8;
        size_t ob0 = (size_t)(w * 64 + i0) * DIMC + h * 32;
        size_t ob1 = (size_t)(w * 64 + i1) * DIMC + h * 32;
#pragma unroll
        for (int ni = 0; ni < 2; ni++) {
            int d0 = wd + ni * 8 + (tig << 1);
            *(float2*)&out[ob0 + d0] = make_float2(rtf(oacc[ni][0]), rtf(oacc[ni][1]));
            *(float2*)&out[ob1 + d0] = make_float2(rtf(oacc[ni][2]), rtf(oacc[ni][3]));
        }
    }
}

// ---------------- launch ----------------
extern "C" void kernel_launch(void* const* d_in, const int* in_sizes, int n_in,
                              void* d_out, int out_size) {
    float *xg, *xn, *qkvb, *attnb, *hb, *wb;
    cudaGetSymbolAddress((void**)&xg, g_x);
    cudaGetSymbolAddress((void**)&xn, g_xn);
    cudaGetSymbolAddress((void**)&qkvb, g_qkv);
    cudaGetSymbolAddress((void**)&attnb, g_attn);
    cudaGetSymbolAddress((void**)&hb, g_h);
    cudaGetSymbolAddress((void**)&wb, g_w);

    cudaFuncSetAttribute(tgemm<0>, cudaFuncAttributeMaxDynamicSharedMemorySize, SMEM_BYTES);
    cudaFuncSetAttribute(tgemm<1>, cudaFuncAttributeMaxDynamicSharedMemorySize, SMEM_BYTES);
    cudaFuncSetAttribute(tgemm<2>, cudaFuncAttributeMaxDynamicSharedMemorySize, SMEM_BYTES);
    cudaFuncSetAttribute(tgemm<3>, cudaFuncAttributeMaxDynamicSharedMemorySize, SMEM_BYTES);

    const float* X = (const float*)d_in[0];
    const int WOFF_P = 196608, WOFF_F1 = 262144, WOFF_F2 = 524288, WSZ = 786432;

    for (int blk = 0; blk < 2; blk++) {
        const float* const* P = (const float* const*)(d_in + 1 + blk * 13);
        cvt4_k<<<786432 / 256, 256>>>(P[2], P[5], P[9], P[11], wb + blk * WSZ);
    }

    for (int blk = 0; blk < 2; blk++) {
        const float* const* P = (const float* const*)(d_in + 1 + blk * 13);
        const float *qkvbias = P[3], *rpb = P[4];
        const float *pb = P[6], *n2g = P[7], *n2b = P[8];
        const float *f1b = P[10], *f2b = P[12];
        const float* W = wb + blk * WSZ;
        int shift = blk ? 4 : 0;

        if (blk == 0) {
            ln_copy_k<<<TOK, 256>>>(X, P[0], P[1], xg, xn);
        }

        tgemm<0><<<dim3(QKVN / 256, TOK / 128), 256, SMEM_BYTES>>>(
            xn, W, qkvbias, qkvb, nullptr, nullptr, nullptr, nullptr, DIMC, QKVN, shift);
        attn_k<<<8192, 256>>>(qkvb, rpb, attnb, blk);
        tgemm<1><<<dim3(DIMC / 256, TOK / 128), 256, SMEM_BYTES>>>(
            attnb, W + WOFF_P, pb, xg, nullptr, n2g, n2b, xn, DIMC, DIMC, shift);
        tgemm<2><<<dim3(MLPH / 256, TOK / 128), 256, SMEM_BYTES>>>(
            xn, W + WOFF_F1, f1b, hb, nullptr, nullptr, nullptr, nullptr, DIMC, MLPH, 0);
        if (blk == 0) {
            const float* const* P1 = (const float* const*)(d_in + 1 + 13);
            tgemm<3><<<dim3(DIMC / 256, TOK / 128), 256, SMEM_BYTES>>>(
                hb, W + WOFF_F2, f2b, xg, xg, P1[0], P1[1], xn, MLPH, DIMC, 0);
        } else {
            tgemm<3><<<dim3(DIMC / 256, TOK / 128), 256, SMEM_BYTES>>>(
                hb, W + WOFF_F2, f2b, (float*)d_out, xg, nullptr, nullptr, nullptr, MLPH, DIMC, 0);
        }
    }
}